// round 13
// baseline (speedup 1.0000x reference)
#include <cuda_runtime.h>
#include <cuda_bf16.h>
#include <cstdint>

#define TPB  256
#define NT   64
#define C_IN 256

// ---------------- smem byte offsets (total 57344) ----------------
#define XF_OFF   0u        // X frag chunk [8ks][8nt][32]uint4 = 32768 (staged twice)
#define SC_OFF   0u        // y scratch 64 x 68 f32 = 17408 (reuses XF after P1)
#define ZF_OFF   32768u    // Z frags uint4 [6ks][8nt][32] = 24576 (ends 57344)
#define SMEM_BYTES 57344u

// ---------------- fragment-ordered weights (prep output, validated) ----------------
__device__ uint4 g_A1h[3 * 4 * 16 * 32];
__device__ uint4 g_A1l[3 * 4 * 16 * 32];
__device__ uint4 g_A2h[3 * 16 * 6 * 32];
__device__ uint4 g_A2l[3 * 16 * 6 * 32];

__device__ __forceinline__ void split_bf(float v, unsigned short& h, unsigned short& l) {
    __nv_bfloat16 bh = __float2bfloat16_rn(v);
    h = __bfloat16_as_ushort(bh);
    l = __bfloat16_as_ushort(__float2bfloat16_rn(v - __bfloat162float(bh)));
}
__device__ __forceinline__ unsigned pack2u(unsigned short a, unsigned short b) {
    return (unsigned)a | ((unsigned)b << 16);
}

// vectorized split: returns {hi packed (v1<<16|v0), lo packed} — bit-identical to
// pack2u(split_bf(v0), split_bf(v1)) since cvt.rn.bf16x2 uses round-nearest-even.
__device__ __forceinline__ uint2 split_pair(float v0, float v1) {
    unsigned hp;
    asm("cvt.rn.bf16x2.f32 %0, %1, %2;" : "=r"(hp) : "f"(v1), "f"(v0));
    const float h0 = __uint_as_float(hp << 16);
    const float h1 = __uint_as_float(hp & 0xffff0000u);
    const float l0 = v0 - h0, l1 = v1 - h1;
    unsigned lp;
    asm("cvt.rn.bf16x2.f32 %0, %1, %2;" : "=r"(lp) : "f"(l1), "f"(l0));
    return make_uint2(hp, lp);
}

__device__ __forceinline__ void mma_bf(float* c, const uint4& a, unsigned b0, unsigned b1) {
    asm volatile(
        "mma.sync.aligned.m16n8k16.row.col.f32.bf16.bf16.f32 "
        "{%0,%1,%2,%3}, {%4,%5,%6,%7}, {%8,%9}, {%0,%1,%2,%3};"
        : "+f"(c[0]), "+f"(c[1]), "+f"(c[2]), "+f"(c[3])
        : "r"(a.x), "r"(a.y), "r"(a.z), "r"(a.w), "r"(b0), "r"(b1));
}

// ---------------- prep: fragment + split weights (unchanged, validated) ----------------
__global__ void prep_kernel(const float* __restrict__ W1_0, const float* __restrict__ W1_1,
                            const float* __restrict__ W1_2,
                            const float* __restrict__ W2_0, const float* __restrict__ W2_1,
                            const float* __restrict__ W2_2)
{
    const int idx = blockIdx.x * blockDim.x + threadIdx.x;
    const int N1 = 3 * 4 * 16 * 32;
    const int N2 = 3 * 16 * 6 * 32;
    if (idx < N1) {
        const int lane = idx & 31, ks = (idx >> 5) & 15, mt = (idx >> 9) & 3, l = idx >> 11;
        const float* W1 = (l == 0) ? W1_0 : (l == 1) ? W1_1 : W1_2;
        const int r0 = mt * 16 + (lane >> 2);
        const int c0 = ks * 16 + (lane & 3) * 2;
        unsigned short h[8], lo[8];
        split_bf(W1[(c0    ) * 64 + r0    ], h[0], lo[0]);
        split_bf(W1[(c0 + 1) * 64 + r0    ], h[1], lo[1]);
        split_bf(W1[(c0    ) * 64 + r0 + 8], h[2], lo[2]);
        split_bf(W1[(c0 + 1) * 64 + r0 + 8], h[3], lo[3]);
        split_bf(W1[(c0 + 8) * 64 + r0    ], h[4], lo[4]);
        split_bf(W1[(c0 + 9) * 64 + r0    ], h[5], lo[5]);
        split_bf(W1[(c0 + 8) * 64 + r0 + 8], h[6], lo[6]);
        split_bf(W1[(c0 + 9) * 64 + r0 + 8], h[7], lo[7]);
        g_A1h[idx] = make_uint4(pack2u(h[0], h[1]), pack2u(h[2], h[3]),
                                pack2u(h[4], h[5]), pack2u(h[6], h[7]));
        g_A1l[idx] = make_uint4(pack2u(lo[0], lo[1]), pack2u(lo[2], lo[3]),
                                pack2u(lo[4], lo[5]), pack2u(lo[6], lo[7]));
    } else if (idx < N1 + N2) {
        const int i2 = idx - N1;
        const int lane = i2 & 31;
        const int rest = i2 >> 5;
        const int ks = rest % 6;
        const int mt = (rest / 6) & 15;
        const int l  = rest / 96;
        const float* W2 = (l == 0) ? W2_0 : (l == 1) ? W2_1 : W2_2;
        const int r0 = mt * 16 + (lane >> 2);
        const int c0 = ks * 16 + (lane & 3) * 2;
        unsigned short h[8], lo[8];
        split_bf(W2[(c0    ) * 256 + r0    ], h[0], lo[0]);
        split_bf(W2[(c0 + 1) * 256 + r0    ], h[1], lo[1]);
        split_bf(W2[(c0    ) * 256 + r0 + 8], h[2], lo[2]);
        split_bf(W2[(c0 + 1) * 256 + r0 + 8], h[3], lo[3]);
        split_bf(W2[(c0 + 8) * 256 + r0    ], h[4], lo[4]);
        split_bf(W2[(c0 + 9) * 256 + r0    ], h[5], lo[5]);
        split_bf(W2[(c0 + 8) * 256 + r0 + 8], h[6], lo[6]);
        split_bf(W2[(c0 + 9) * 256 + r0 + 8], h[7], lo[7]);
        g_A2h[i2] = make_uint4(pack2u(h[0], h[1]), pack2u(h[2], h[3]),
                               pack2u(h[4], h[5]), pack2u(h[6], h[7]));
        g_A2l[i2] = make_uint4(pack2u(lo[0], lo[1]), pack2u(lo[2], lo[3]),
                               pack2u(lo[4], lo[5]), pack2u(lo[6], lo[7]));
    }
}

__global__ void __launch_bounds__(TPB, 3)
fused_mma_kernel(const float* __restrict__ x0, const float* __restrict__ x1,
                 const float* __restrict__ x2,
                 const float* __restrict__ b1_0, const float* __restrict__ b2_0,
                 const float* __restrict__ b1_1, const float* __restrict__ b2_1,
                 const float* __restrict__ b1_2, const float* __restrict__ b2_2,
                 float* __restrict__ out)
{
    extern __shared__ char smc[];
    const int tid  = threadIdx.x;
    const int w    = tid >> 5;
    const int lane = tid & 31;

    // ---- level select (tiles of 64 px: 1024 | 256 | 64) ----
    const int t = blockIdx.x;
    const float *x, *b1, *b2;
    float* o;
    int npix, tl, lvl;
    if (t < 1024)      { x = x0; b1 = b1_0; b2 = b2_0; o = out;             npix = 16384; tl = t;        lvl = 0; }
    else if (t < 1280) { x = x1; b1 = b1_1; b2 = b2_1; o = out + 16777216L; npix = 4096;  tl = t - 1024; lvl = 1; }
    else               { x = x2; b1 = b1_2; b2 = b2_2; o = out + 20971520L; npix = 1024;  tl = t - 1280; lvl = 2; }

    const int tpi  = npix / NT;
    const int img  = tl / tpi;
    const int p0   = (tl - img * tpi) * NT;
    const long ibase = (long)img * C_IN * npix + p0;

    uint4*  sXf = (uint4*)(smc + XF_OFF);
    uint4*  sZf = (uint4*)(smc + ZF_OFF);
    float*  sSc = (float*)(smc + SC_OFF);

    // ---- P1 warp identity: wr = mt-pair, nh = N quarter (nt pair) ----
    const int wr = w & 1;
    const int nh = w >> 1;          // 0..3
    float acc1[16];                 // [i(2)][j(2)][4] — accumulates across BOTH K chunks
    #pragma unroll
    for (int i = 0; i < 16; ++i) acc1[i] = 0.0f;

    const uint4* A1h = g_A1h + ((lvl * 4 + wr * 2) * 16) * 32 + lane;
    const uint4* A1l = g_A1l + ((lvl * 4 + wr * 2) * 16) * 32 + lane;

    // ================= phase 1: two temporal K-chunks of 8 ks =================
    #pragma unroll 1
    for (int ch = 0; ch < 2; ++ch) {
        // ---- stage X fragment chunk [8ks][8nt] (hi/lo fused uint4) ----
        #pragma unroll
        for (int it = 0; it < 2; ++it) {
            const int idx = tid + it * TPB;         // 512 items
            const int kp = idx & 3, j = (idx >> 2) & 1, nt = (idx >> 3) & 7, k8 = idx >> 6;
            const int c0 = (ch * 8 + k8) * 16 + 2 * kp;
            const int p  = nt * 8 + 4 * j;
            const float4 r0 = __ldcs((const float4*)(x + ibase + (long)(c0    ) * npix + p));
            const float4 r1 = __ldcs((const float4*)(x + ibase + (long)(c0 + 1) * npix + p));
            const float4 r2 = __ldcs((const float4*)(x + ibase + (long)(c0 + 8) * npix + p));
            const float4 r3 = __ldcs((const float4*)(x + ibase + (long)(c0 + 9) * npix + p));
            const float v0[4] = {r0.x, r0.y, r0.z, r0.w};
            const float v1[4] = {r1.x, r1.y, r1.z, r1.w};
            const float v2[4] = {r2.x, r2.y, r2.z, r2.w};
            const float v3[4] = {r3.x, r3.y, r3.z, r3.w};
            const int base = (k8 * 8 + nt) * 32;
            #pragma unroll
            for (int q = 0; q < 4; ++q) {
                const uint2 p01 = split_pair(v0[q], v1[q]);
                const uint2 p23 = split_pair(v2[q], v3[q]);
                sXf[base + (4 * j + q) * 4 + kp] = make_uint4(p01.x, p23.x, p01.y, p23.y);
            }
        }
        __syncthreads();

        // ---- MMA over this chunk ----
        #pragma unroll 4
        for (int k8 = 0; k8 < 8; ++k8) {
            const int ks = ch * 8 + k8;
            const uint4 ah0 = __ldg(A1h + ks * 32);
            const uint4 al0 = __ldg(A1l + ks * 32);
            const uint4 ah1 = __ldg(A1h + (16 + ks) * 32);
            const uint4 al1 = __ldg(A1l + (16 + ks) * 32);
            #pragma unroll
            for (int j = 0; j < 2; ++j) {
                const uint4 f = sXf[(k8 * 8 + nh * 2 + j) * 32 + lane];
                mma_bf(acc1 + j * 4,     ah0, f.x, f.y);
                mma_bf(acc1 + 8 + j * 4, ah1, f.x, f.y);
                mma_bf(acc1 + j * 4,     ah0, f.z, f.w);
                mma_bf(acc1 + 8 + j * 4, ah1, f.z, f.w);
                mma_bf(acc1 + j * 4,     al0, f.x, f.y);
                mma_bf(acc1 + 8 + j * 4, al1, f.x, f.y);
            }
        }
        __syncthreads();   // chunk consumed (before restage / before SC overlays XF)
    }

    // ---- phase-1 epilogue: y = acc + b1 -> scratch [64][68] (full K per warp) ----
    {
        #pragma unroll
        for (int i = 0; i < 2; ++i) {
            const int r0 = (wr * 2 + i) * 16 + (lane >> 2), r1 = r0 + 8;
            const float bias0 = __ldg(b1 + r0);
            const float bias1 = __ldg(b1 + r1);
            #pragma unroll
            for (int j = 0; j < 2; ++j) {
                const int col = (nh * 2 + j) * 8 + (lane & 3) * 2;
                const float* a = acc1 + i * 8 + j * 4;
                *(float2*)(sSc + r0 * 68 + col) = make_float2(a[0] + bias0, a[1] + bias0);
                *(float2*)(sSc + r1 * 68 + col) = make_float2(a[2] + bias1, a[3] + bias1);
            }
        }
    }
    __syncthreads();

    // ---- build Z fragments: rows 0..63 = y, 64..95 = relu(y[32..63]) ----
    #pragma unroll
    for (int it = 0; it < 2; ++it) {
        const int idx = tid + it * TPB;
        if (idx < 384) {
            const int kp = idx & 3, j = (idx >> 2) & 1, nt = (idx >> 3) & 7, ks = idx >> 6;
            const int p = nt * 8 + 4 * j;
            float v[4][4];
            #pragma unroll
            for (int e = 0; e < 4; ++e) {
                const int zc = ks * 16 + 2 * kp + ((e >> 1) ? 8 : 0) + (e & 1);
                const int yr = (zc < 64) ? zc : (zc - 32);
                float4 yv = *(const float4*)(sSc + yr * 68 + p);
                if (zc >= 64) {
                    yv.x = fmaxf(yv.x, 0.f); yv.y = fmaxf(yv.y, 0.f);
                    yv.z = fmaxf(yv.z, 0.f); yv.w = fmaxf(yv.w, 0.f);
                }
                v[e][0] = yv.x; v[e][1] = yv.y; v[e][2] = yv.z; v[e][3] = yv.w;
            }
            const int base = (ks * 8 + nt) * 32;
            #pragma unroll
            for (int q = 0; q < 4; ++q) {
                const uint2 p01 = split_pair(v[0][q], v[1][q]);
                const uint2 p23 = split_pair(v[2][q], v[3][q]);
                sZf[base + (4 * j + q) * 4 + kp] = make_uint4(p01.x, p23.x, p01.y, p23.y);
            }
        }
    }
    __syncthreads();

    // ======= phase 2: warp owns M=32 (mt pair w) x all N=64, two halves of 4 nt =======
    {
        const uint4* Ah = g_A2h + ((lvl * 16 + w * 2) * 6) * 32 + lane;
        const uint4* Al = g_A2l + ((lvl * 16 + w * 2) * 6) * 32 + lane;
        const int ch0 = (w * 2) * 16 + (lane >> 2);
        const float bias00 = __ldg(b2 + ch0);
        const float bias01 = __ldg(b2 + ch0 + 8);
        const float bias10 = __ldg(b2 + ch0 + 16);
        const float bias11 = __ldg(b2 + ch0 + 24);

        #pragma unroll
        for (int iter = 0; iter < 2; ++iter) {
            float acc2[32];                      // [i(2)][n(4)][4]
            #pragma unroll
            for (int i = 0; i < 32; ++i) acc2[i] = 0.0f;

            #pragma unroll
            for (int ks = 0; ks < 6; ++ks) {
                const uint4 ah0 = __ldg(Ah + ks * 32);
                const uint4 al0 = __ldg(Al + ks * 32);
                const uint4 ah1 = __ldg(Ah + (6 + ks) * 32);
                const uint4 al1 = __ldg(Al + (6 + ks) * 32);
                #pragma unroll
                for (int n = 0; n < 4; ++n) {
                    const int nt = iter * 4 + n;
                    const uint4 f = sZf[(ks * 8 + nt) * 32 + lane];
                    mma_bf(acc2 + n * 4,      ah0, f.x, f.y);
                    mma_bf(acc2 + 16 + n * 4, ah1, f.x, f.y);
                    mma_bf(acc2 + n * 4,      ah0, f.z, f.w);
                    mma_bf(acc2 + 16 + n * 4, ah1, f.z, f.w);
                    mma_bf(acc2 + n * 4,      al0, f.x, f.y);
                    mma_bf(acc2 + 16 + n * 4, al1, f.x, f.y);
                }
            }

            // epilogue for this 32-px half (streaming stores)
            #pragma unroll
            for (int i = 0; i < 2; ++i) {
                const int cA = ch0 + i * 16, cB = cA + 8;
                const float bA = i ? bias10 : bias00;
                const float bB = i ? bias11 : bias01;
                float* oA = o + ibase + (long)cA * npix;
                float* oB = o + ibase + (long)cB * npix;
                #pragma unroll
                for (int n = 0; n < 4; ++n) {
                    const int px = (iter * 4 + n) * 8 + (lane & 3) * 2;
                    const float* a = acc2 + i * 16 + n * 4;
                    __stcs((float2*)(oA + px), make_float2(a[0] + bA, a[1] + bA));
                    __stcs((float2*)(oB + px), make_float2(a[2] + bB, a[3] + bB));
                }
            }
        }
    }
}

extern "C" void kernel_launch(void* const* d_in, const int* in_sizes, int n_in,
                              void* d_out, int out_size)
{
    const float* x0   = (const float*)d_in[0];
    const float* x1   = (const float*)d_in[1];
    const float* x2   = (const float*)d_in[2];
    const float* W1_0 = (const float*)d_in[3];
    const float* b1_0 = (const float*)d_in[4];
    const float* W2_0 = (const float*)d_in[5];
    const float* b2_0 = (const float*)d_in[6];
    const float* W1_1 = (const float*)d_in[7];
    const float* b1_1 = (const float*)d_in[8];
    const float* W2_1 = (const float*)d_in[9];
    const float* b2_1 = (const float*)d_in[10];
    const float* W1_2 = (const float*)d_in[11];
    const float* b1_2 = (const float*)d_in[12];
    const float* W2_2 = (const float*)d_in[13];
    const float* b2_2 = (const float*)d_in[14];

    const int total = 3 * 4 * 16 * 32 + 3 * 16 * 6 * 32;
    prep_kernel<<<(total + 255) / 256, 256>>>(W1_0, W1_1, W1_2, W2_0, W2_1, W2_2);

    cudaFuncSetAttribute(fused_mma_kernel,
                         cudaFuncAttributeMaxDynamicSharedMemorySize, SMEM_BYTES);

    // 1344 tiles of 64 pixels: 1024 (level0) + 256 (level1) + 64 (level2)
    fused_mma_kernel<<<1344, TPB, SMEM_BYTES>>>(
        x0, x1, x2,
        b1_0, b2_0, b1_1, b2_1, b1_2, b2_2,
        (float*)d_out);
}

// round 15
// speedup vs baseline: 1.0452x; 1.0452x over previous
#include <cuda_runtime.h>
#include <cuda_bf16.h>
#include <cstdint>

#define TPB  256
#define NT   64
#define C_IN 256

// ---------------- smem byte offsets (total 65536) ----------------
#define XF_OFF   0u        // X frags uint4 [16ks][8nt][32] = 65536 (full)
#define SC_OFF   0u        // y scratch 64 x 68 f32 = 17408 (reuses XF after dead)
#define ZF_OFF   17408u    // Z frags uint4 [6ks][8nt][32] = 24576 (ends 41984)
#define RB_OFF   32768u    // phase-1 K-split reduction buffer, 16384B
#define SMEM_BYTES 65536u

// ---------------- fragment-ordered weights (prep output, validated) ----------------
__device__ uint4 g_A1h[3 * 4 * 16 * 32];
__device__ uint4 g_A1l[3 * 4 * 16 * 32];
__device__ uint4 g_A2h[3 * 16 * 6 * 32];
__device__ uint4 g_A2l[3 * 16 * 6 * 32];

__device__ __forceinline__ void split_bf(float v, unsigned short& h, unsigned short& l) {
    __nv_bfloat16 bh = __float2bfloat16_rn(v);
    h = __bfloat16_as_ushort(bh);
    l = __bfloat16_as_ushort(__float2bfloat16_rn(v - __bfloat162float(bh)));
}
__device__ __forceinline__ unsigned pack2u(unsigned short a, unsigned short b) {
    return (unsigned)a | ((unsigned)b << 16);
}

// vectorized split (validated R13): {hi packed (v1<<16|v0), lo packed},
// bit-identical to pack2u(split_bf(v0), split_bf(v1)).
__device__ __forceinline__ uint2 split_pair(float v0, float v1) {
    unsigned hp;
    asm("cvt.rn.bf16x2.f32 %0, %1, %2;" : "=r"(hp) : "f"(v1), "f"(v0));
    const float h0 = __uint_as_float(hp << 16);
    const float h1 = __uint_as_float(hp & 0xffff0000u);
    const float l0 = v0 - h0, l1 = v1 - h1;
    unsigned lp;
    asm("cvt.rn.bf16x2.f32 %0, %1, %2;" : "=r"(lp) : "f"(l1), "f"(l0));
    return make_uint2(hp, lp);
}

// non-volatile: register-pure op, lets the compiler interleave with LDS/LDG
__device__ __forceinline__ void mma_bf(float* c, const uint4& a, unsigned b0, unsigned b1) {
    asm("mma.sync.aligned.m16n8k16.row.col.f32.bf16.bf16.f32 "
        "{%0,%1,%2,%3}, {%4,%5,%6,%7}, {%8,%9}, {%0,%1,%2,%3};"
        : "+f"(c[0]), "+f"(c[1]), "+f"(c[2]), "+f"(c[3])
        : "r"(a.x), "r"(a.y), "r"(a.z), "r"(a.w), "r"(b0), "r"(b1));
}

// ---------------- prep: fragment + split weights (unchanged, validated) ----------------
__global__ void prep_kernel(const float* __restrict__ W1_0, const float* __restrict__ W1_1,
                            const float* __restrict__ W1_2,
                            const float* __restrict__ W2_0, const float* __restrict__ W2_1,
                            const float* __restrict__ W2_2)
{
    const int idx = blockIdx.x * blockDim.x + threadIdx.x;
    const int N1 = 3 * 4 * 16 * 32;
    const int N2 = 3 * 16 * 6 * 32;
    if (idx < N1) {
        const int lane = idx & 31, ks = (idx >> 5) & 15, mt = (idx >> 9) & 3, l = idx >> 11;
        const float* W1 = (l == 0) ? W1_0 : (l == 1) ? W1_1 : W1_2;
        const int r0 = mt * 16 + (lane >> 2);
        const int c0 = ks * 16 + (lane & 3) * 2;
        unsigned short h[8], lo[8];
        split_bf(W1[(c0    ) * 64 + r0    ], h[0], lo[0]);
        split_bf(W1[(c0 + 1) * 64 + r0    ], h[1], lo[1]);
        split_bf(W1[(c0    ) * 64 + r0 + 8], h[2], lo[2]);
        split_bf(W1[(c0 + 1) * 64 + r0 + 8], h[3], lo[3]);
        split_bf(W1[(c0 + 8) * 64 + r0    ], h[4], lo[4]);
        split_bf(W1[(c0 + 9) * 64 + r0    ], h[5], lo[5]);
        split_bf(W1[(c0 + 8) * 64 + r0 + 8], h[6], lo[6]);
        split_bf(W1[(c0 + 9) * 64 + r0 + 8], h[7], lo[7]);
        g_A1h[idx] = make_uint4(pack2u(h[0], h[1]), pack2u(h[2], h[3]),
                                pack2u(h[4], h[5]), pack2u(h[6], h[7]));
        g_A1l[idx] = make_uint4(pack2u(lo[0], lo[1]), pack2u(lo[2], lo[3]),
                                pack2u(lo[4], lo[5]), pack2u(lo[6], lo[7]));
    } else if (idx < N1 + N2) {
        const int i2 = idx - N1;
        const int lane = i2 & 31;
        const int rest = i2 >> 5;
        const int ks = rest % 6;
        const int mt = (rest / 6) & 15;
        const int l  = rest / 96;
        const float* W2 = (l == 0) ? W2_0 : (l == 1) ? W2_1 : W2_2;
        const int r0 = mt * 16 + (lane >> 2);
        const int c0 = ks * 16 + (lane & 3) * 2;
        unsigned short h[8], lo[8];
        split_bf(W2[(c0    ) * 256 + r0    ], h[0], lo[0]);
        split_bf(W2[(c0 + 1) * 256 + r0    ], h[1], lo[1]);
        split_bf(W2[(c0    ) * 256 + r0 + 8], h[2], lo[2]);
        split_bf(W2[(c0 + 1) * 256 + r0 + 8], h[3], lo[3]);
        split_bf(W2[(c0 + 8) * 256 + r0    ], h[4], lo[4]);
        split_bf(W2[(c0 + 9) * 256 + r0    ], h[5], lo[5]);
        split_bf(W2[(c0 + 8) * 256 + r0 + 8], h[6], lo[6]);
        split_bf(W2[(c0 + 9) * 256 + r0 + 8], h[7], lo[7]);
        g_A2h[i2] = make_uint4(pack2u(h[0], h[1]), pack2u(h[2], h[3]),
                               pack2u(h[4], h[5]), pack2u(h[6], h[7]));
        g_A2l[i2] = make_uint4(pack2u(lo[0], lo[1]), pack2u(lo[2], lo[3]),
                               pack2u(lo[4], lo[5]), pack2u(lo[6], lo[7]));
    }
}

__global__ void __launch_bounds__(TPB, 2)
fused_mma_kernel(const float* __restrict__ x0, const float* __restrict__ x1,
                 const float* __restrict__ x2,
                 const float* __restrict__ b1_0, const float* __restrict__ b2_0,
                 const float* __restrict__ b1_1, const float* __restrict__ b2_1,
                 const float* __restrict__ b1_2, const float* __restrict__ b2_2,
                 float* __restrict__ out)
{
    extern __shared__ char smc[];
    const int tid  = threadIdx.x;
    const int w    = tid >> 5;
    const int lane = tid & 31;

    // ---- level select (tiles of 64 px: 1024 | 256 | 64) ----
    const int t = blockIdx.x;
    const float *x, *b1, *b2;
    float* o;
    int npix, tl, lvl;
    if (t < 1024)      { x = x0; b1 = b1_0; b2 = b2_0; o = out;             npix = 16384; tl = t;        lvl = 0; }
    else if (t < 1280) { x = x1; b1 = b1_1; b2 = b2_1; o = out + 16777216L; npix = 4096;  tl = t - 1024; lvl = 1; }
    else               { x = x2; b1 = b1_2; b2 = b2_2; o = out + 20971520L; npix = 1024;  tl = t - 1280; lvl = 2; }

    const int tpi  = npix / NT;
    const int img  = tl / tpi;
    const int p0   = (tl - img * tpi) * NT;
    const long ibase = (long)img * C_IN * npix + p0;

    uint4*  sXf = (uint4*)(smc + XF_OFF);
    uint4*  sZf = (uint4*)(smc + ZF_OFF);
    float*  sSc = (float*)(smc + SC_OFF);
    float4* sRb = (float4*)(smc + RB_OFF);

    // ================= stage X fragments (hi/lo fused in uint4) =================
    #pragma unroll
    for (int it = 0; it < 4; ++it) {
        const int idx = tid + it * TPB;
        const int kp = idx & 3, j = (idx >> 2) & 1, nt = (idx >> 3) & 7, ks = idx >> 6;
        const int c0 = ks * 16 + 2 * kp;
        const int p  = nt * 8 + 4 * j;
        const float4 r0 = *(const float4*)(x + ibase + (long)(c0    ) * npix + p);
        const float4 r1 = *(const float4*)(x + ibase + (long)(c0 + 1) * npix + p);
        const float4 r2 = *(const float4*)(x + ibase + (long)(c0 + 8) * npix + p);
        const float4 r3 = *(const float4*)(x + ibase + (long)(c0 + 9) * npix + p);
        const float v0[4] = {r0.x, r0.y, r0.z, r0.w};
        const float v1[4] = {r1.x, r1.y, r1.z, r1.w};
        const float v2[4] = {r2.x, r2.y, r2.z, r2.w};
        const float v3[4] = {r3.x, r3.y, r3.z, r3.w};
        const int base = (ks * 8 + nt) * 32;
        #pragma unroll
        for (int q = 0; q < 4; ++q) {
            const uint2 p01 = split_pair(v0[q], v1[q]);
            const uint2 p23 = split_pair(v2[q], v3[q]);
            sXf[base + (4 * j + q) * 4 + kp] = make_uint4(p01.x, p23.x, p01.y, p23.y);
        }
    }
    __syncthreads();

    // ======= phase 1 MMA: K-split. warp = (wr mt-pair, nh N-half, kh K-half) =======
    const int wr = w & 1;
    const int nh = (w >> 1) & 1;
    const int kh = w >> 2;
    float acc1[32];                  // [i(2)][j(4)][4]
    {
        #pragma unroll
        for (int i = 0; i < 32; ++i) acc1[i] = 0.0f;
        const uint4* Ah = g_A1h + ((lvl * 4 + wr * 2) * 16) * 32 + lane;
        const uint4* Al = g_A1l + ((lvl * 4 + wr * 2) * 16) * 32 + lane;
        #pragma unroll 4
        for (int k8 = 0; k8 < 8; ++k8) {
            const int ks = kh * 8 + k8;
            const uint4 ah0 = __ldg(Ah + ks * 32);
            const uint4 al0 = __ldg(Al + ks * 32);
            const uint4 ah1 = __ldg(Ah + (16 + ks) * 32);
            const uint4 al1 = __ldg(Al + (16 + ks) * 32);
            #pragma unroll
            for (int j = 0; j < 4; ++j) {
                const uint4 f = sXf[(ks * 8 + nh * 4 + j) * 32 + lane];
                mma_bf(acc1 + j * 4,      ah0, f.x, f.y);
                mma_bf(acc1 + 16 + j * 4, ah1, f.x, f.y);
                mma_bf(acc1 + j * 4,      ah0, f.z, f.w);
                mma_bf(acc1 + 16 + j * 4, ah1, f.z, f.w);
                mma_bf(acc1 + j * 4,      al0, f.x, f.y);
                mma_bf(acc1 + 16 + j * 4, al1, f.x, f.y);
            }
        }
    }
    __syncthreads();   // XF reads done; region reusable

    // ---- K-split reduction: kh=1 warps park partials in smem ----
    if (kh == 1) {
        #pragma unroll
        for (int i = 0; i < 2; ++i)
            #pragma unroll
            for (int j = 0; j < 4; ++j)
                sRb[((((wr * 2 + nh) * 2) + i) * 4 + j) * 32 + lane] =
                    make_float4(acc1[i * 16 + j * 4 + 0], acc1[i * 16 + j * 4 + 1],
                                acc1[i * 16 + j * 4 + 2], acc1[i * 16 + j * 4 + 3]);
    }
    __syncthreads();

    // ---- kh=0 warps: add partials + bias -> y scratch [64][68] ----
    if (kh == 0) {
        #pragma unroll
        for (int i = 0; i < 2; ++i) {
            const int r0 = (wr * 2 + i) * 16 + (lane >> 2), r1 = r0 + 8;
            const float bias0 = __ldg(b1 + r0);
            const float bias1 = __ldg(b1 + r1);
            #pragma unroll
            for (int j = 0; j < 4; ++j) {
                const float4 p = sRb[((((wr * 2 + nh) * 2) + i) * 4 + j) * 32 + lane];
                const int col = (nh * 4 + j) * 8 + (lane & 3) * 2;
                const float* a = acc1 + i * 16 + j * 4;
                *(float2*)(sSc + r0 * 68 + col) =
                    make_float2(a[0] + p.x + bias0, a[1] + p.y + bias0);
                *(float2*)(sSc + r1 * 68 + col) =
                    make_float2(a[2] + p.z + bias1, a[3] + p.w + bias1);
            }
        }
    }
    __syncthreads();

    // ---- build Z fragments: rows 0..63 = y, 64..95 = relu(y[32..63]) ----
    #pragma unroll
    for (int it = 0; it < 2; ++it) {
        const int idx = tid + it * TPB;
        if (idx < 384) {
            const int kp = idx & 3, j = (idx >> 2) & 1, nt = (idx >> 3) & 7, ks = idx >> 6;
            const int p = nt * 8 + 4 * j;
            float v[4][4];
            #pragma unroll
            for (int e = 0; e < 4; ++e) {
                const int zc = ks * 16 + 2 * kp + ((e >> 1) ? 8 : 0) + (e & 1);
                const int yr = (zc < 64) ? zc : (zc - 32);
                float4 yv = *(const float4*)(sSc + yr * 68 + p);
                if (zc >= 64) {
                    yv.x = fmaxf(yv.x, 0.f); yv.y = fmaxf(yv.y, 0.f);
                    yv.z = fmaxf(yv.z, 0.f); yv.w = fmaxf(yv.w, 0.f);
                }
                v[e][0] = yv.x; v[e][1] = yv.y; v[e][2] = yv.z; v[e][3] = yv.w;
            }
            const int base = (ks * 8 + nt) * 32;
            #pragma unroll
            for (int q = 0; q < 4; ++q) {
                const uint2 p01 = split_pair(v[0][q], v[1][q]);
                const uint2 p23 = split_pair(v[2][q], v[3][q]);
                sZf[base + (4 * j + q) * 4 + kp] = make_uint4(p01.x, p23.x, p01.y, p23.y);
            }
        }
    }
    __syncthreads();

    // ======= phase 2: warp owns M=32 (mt pair w) x all N=64, two halves of 4 nt =======
    {
        const uint4* Ah = g_A2h + ((lvl * 16 + w * 2) * 6) * 32 + lane;
        const uint4* Al = g_A2l + ((lvl * 16 + w * 2) * 6) * 32 + lane;
        const int ch0 = (w * 2) * 16 + (lane >> 2);
        const float bias00 = __ldg(b2 + ch0);
        const float bias01 = __ldg(b2 + ch0 + 8);
        const float bias10 = __ldg(b2 + ch0 + 16);
        const float bias11 = __ldg(b2 + ch0 + 24);

        #pragma unroll
        for (int iter = 0; iter < 2; ++iter) {
            float acc2[32];                      // [i(2)][n(4)][4]
            #pragma unroll
            for (int i = 0; i < 32; ++i) acc2[i] = 0.0f;

            #pragma unroll
            for (int ks = 0; ks < 6; ++ks) {
                const uint4 ah0 = __ldg(Ah + ks * 32);
                const uint4 al0 = __ldg(Al + ks * 32);
                const uint4 ah1 = __ldg(Ah + (6 + ks) * 32);
                const uint4 al1 = __ldg(Al + (6 + ks) * 32);
                #pragma unroll
                for (int n = 0; n < 4; ++n) {
                    const int nt = iter * 4 + n;
                    const uint4 f = sZf[(ks * 8 + nt) * 32 + lane];
                    mma_bf(acc2 + n * 4,      ah0, f.x, f.y);
                    mma_bf(acc2 + 16 + n * 4, ah1, f.x, f.y);
                    mma_bf(acc2 + n * 4,      ah0, f.z, f.w);
                    mma_bf(acc2 + 16 + n * 4, ah1, f.z, f.w);
                    mma_bf(acc2 + n * 4,      al0, f.x, f.y);
                    mma_bf(acc2 + 16 + n * 4, al1, f.x, f.y);
                }
            }

            // epilogue for this 32-px half
            #pragma unroll
            for (int i = 0; i < 2; ++i) {
                const int cA = ch0 + i * 16, cB = cA + 8;
                const float bA = i ? bias10 : bias00;
                const float bB = i ? bias11 : bias01;
                float* oA = o + ibase + (long)cA * npix;
                float* oB = o + ibase + (long)cB * npix;
                #pragma unroll
                for (int n = 0; n < 4; ++n) {
                    const int px = (iter * 4 + n) * 8 + (lane & 3) * 2;
                    const float* a = acc2 + i * 16 + n * 4;
                    *(float2*)(oA + px) = make_float2(a[0] + bA, a[1] + bA);
                    *(float2*)(oB + px) = make_float2(a[2] + bB, a[3] + bB);
                }
            }
        }
    }
}

extern "C" void kernel_launch(void* const* d_in, const int* in_sizes, int n_in,
                              void* d_out, int out_size)
{
    const float* x0   = (const float*)d_in[0];
    const float* x1   = (const float*)d_in[1];
    const float* x2   = (const float*)d_in[2];
    const float* W1_0 = (const float*)d_in[3];
    const float* b1_0 = (const float*)d_in[4];
    const float* W2_0 = (const float*)d_in[5];
    const float* b2_0 = (const float*)d_in[6];
    const float* W1_1 = (const float*)d_in[7];
    const float* b1_1 = (const float*)d_in[8];
    const float* W2_1 = (const float*)d_in[9];
    const float* b2_1 = (const float*)d_in[10];
    const float* W1_2 = (const float*)d_in[11];
    const float* b1_2 = (const float*)d_in[12];
    const float* W2_2 = (const float*)d_in[13];
    const float* b2_2 = (const float*)d_in[14];

    const int total = 3 * 4 * 16 * 32 + 3 * 16 * 6 * 32;
    prep_kernel<<<(total + 255) / 256, 256>>>(W1_0, W1_1, W1_2, W2_0, W2_1, W2_2);

    cudaFuncSetAttribute(fused_mma_kernel,
                         cudaFuncAttributeMaxDynamicSharedMemorySize, SMEM_BYTES);

    // 1344 tiles of 64 pixels: 1024 (level0) + 256 (level1) + 64 (level2)
    fused_mma_kernel<<<1344, TPB, SMEM_BYTES>>>(
        x0, x1, x2,
        b1_0, b2_0, b1_1, b2_1, b1_2, b2_2,
        (float*)d_out);
}

// round 16
// speedup vs baseline: 1.5545x; 1.4873x over previous
#include <cuda_runtime.h>
#include <cuda_bf16.h>
#include <cstdint>

#define TPB  256
#define NT   64
#define C_IN 256

// ---------------- smem byte offsets (total 65536) ----------------
#define XF_OFF   0u        // X frags uint4 [16ks][8nt][32] = 65536 (full)
#define SC_OFF   0u        // y scratch 64 x 68 f32 = 17408 (reuses XF after dead)
#define ZF_OFF   17408u    // Z frags uint4 [6ks][8nt][32] = 24576 (ends 41984)
#define RB_OFF   32768u    // phase-1 K-split reduction buffer, 16384B
#define SMEM_BYTES 65536u

// ---------------- fragment-ordered weights (prep output, validated) ----------------
__device__ uint4 g_A1h[3 * 4 * 16 * 32];
__device__ uint4 g_A1l[3 * 4 * 16 * 32];
__device__ uint4 g_A2h[3 * 16 * 6 * 32];
__device__ uint4 g_A2l[3 * 16 * 6 * 32];

__device__ __forceinline__ void split_bf(float v, unsigned short& h, unsigned short& l) {
    __nv_bfloat16 bh = __float2bfloat16_rn(v);
    h = __bfloat16_as_ushort(bh);
    l = __bfloat16_as_ushort(__float2bfloat16_rn(v - __bfloat162float(bh)));
}
__device__ __forceinline__ unsigned pack2u(unsigned short a, unsigned short b) {
    return (unsigned)a | ((unsigned)b << 16);
}

// vectorized split (validated bit-identical R13/R14): {hi packed (v1<<16|v0), lo packed}
__device__ __forceinline__ uint2 split_pair(float v0, float v1) {
    unsigned hp;
    asm("cvt.rn.bf16x2.f32 %0, %1, %2;" : "=r"(hp) : "f"(v1), "f"(v0));
    const float h0 = __uint_as_float(hp << 16);
    const float h1 = __uint_as_float(hp & 0xffff0000u);
    const float l0 = v0 - h0, l1 = v1 - h1;
    unsigned lp;
    asm("cvt.rn.bf16x2.f32 %0, %1, %2;" : "=r"(lp) : "f"(l1), "f"(l0));
    return make_uint2(hp, lp);
}

// VOLATILE: strict order is what keeps live ranges short (R14/R15 spill lesson)
__device__ __forceinline__ void mma_bf(float* c, const uint4& a, unsigned b0, unsigned b1) {
    asm volatile(
        "mma.sync.aligned.m16n8k16.row.col.f32.bf16.bf16.f32 "
        "{%0,%1,%2,%3}, {%4,%5,%6,%7}, {%8,%9}, {%0,%1,%2,%3};"
        : "+f"(c[0]), "+f"(c[1]), "+f"(c[2]), "+f"(c[3])
        : "r"(a.x), "r"(a.y), "r"(a.z), "r"(a.w), "r"(b0), "r"(b1));
}

// ---------------- prep: fragment + split weights (unchanged, validated) ----------------
__global__ void prep_kernel(const float* __restrict__ W1_0, const float* __restrict__ W1_1,
                            const float* __restrict__ W1_2,
                            const float* __restrict__ W2_0, const float* __restrict__ W2_1,
                            const float* __restrict__ W2_2)
{
    const int idx = blockIdx.x * blockDim.x + threadIdx.x;
    const int N1 = 3 * 4 * 16 * 32;
    const int N2 = 3 * 16 * 6 * 32;
    if (idx < N1) {
        const int lane = idx & 31, ks = (idx >> 5) & 15, mt = (idx >> 9) & 3, l = idx >> 11;
        const float* W1 = (l == 0) ? W1_0 : (l == 1) ? W1_1 : W1_2;
        const int r0 = mt * 16 + (lane >> 2);
        const int c0 = ks * 16 + (lane & 3) * 2;
        unsigned short h[8], lo[8];
        split_bf(W1[(c0    ) * 64 + r0    ], h[0], lo[0]);
        split_bf(W1[(c0 + 1) * 64 + r0    ], h[1], lo[1]);
        split_bf(W1[(c0    ) * 64 + r0 + 8], h[2], lo[2]);
        split_bf(W1[(c0 + 1) * 64 + r0 + 8], h[3], lo[3]);
        split_bf(W1[(c0 + 8) * 64 + r0    ], h[4], lo[4]);
        split_bf(W1[(c0 + 9) * 64 + r0    ], h[5], lo[5]);
        split_bf(W1[(c0 + 8) * 64 + r0 + 8], h[6], lo[6]);
        split_bf(W1[(c0 + 9) * 64 + r0 + 8], h[7], lo[7]);
        g_A1h[idx] = make_uint4(pack2u(h[0], h[1]), pack2u(h[2], h[3]),
                                pack2u(h[4], h[5]), pack2u(h[6], h[7]));
        g_A1l[idx] = make_uint4(pack2u(lo[0], lo[1]), pack2u(lo[2], lo[3]),
                                pack2u(lo[4], lo[5]), pack2u(lo[6], lo[7]));
    } else if (idx < N1 + N2) {
        const int i2 = idx - N1;
        const int lane = i2 & 31;
        const int rest = i2 >> 5;
        const int ks = rest % 6;
        const int mt = (rest / 6) & 15;
        const int l  = rest / 96;
        const float* W2 = (l == 0) ? W2_0 : (l == 1) ? W2_1 : W2_2;
        const int r0 = mt * 16 + (lane >> 2);
        const int c0 = ks * 16 + (lane & 3) * 2;
        unsigned short h[8], lo[8];
        split_bf(W2[(c0    ) * 256 + r0    ], h[0], lo[0]);
        split_bf(W2[(c0 + 1) * 256 + r0    ], h[1], lo[1]);
        split_bf(W2[(c0    ) * 256 + r0 + 8], h[2], lo[2]);
        split_bf(W2[(c0 + 1) * 256 + r0 + 8], h[3], lo[3]);
        split_bf(W2[(c0 + 8) * 256 + r0    ], h[4], lo[4]);
        split_bf(W2[(c0 + 9) * 256 + r0    ], h[5], lo[5]);
        split_bf(W2[(c0 + 8) * 256 + r0 + 8], h[6], lo[6]);
        split_bf(W2[(c0 + 9) * 256 + r0 + 8], h[7], lo[7]);
        g_A2h[i2] = make_uint4(pack2u(h[0], h[1]), pack2u(h[2], h[3]),
                               pack2u(h[4], h[5]), pack2u(h[6], h[7]));
        g_A2l[i2] = make_uint4(pack2u(lo[0], lo[1]), pack2u(lo[2], lo[3]),
                               pack2u(lo[4], lo[5]), pack2u(lo[6], lo[7]));
    }
}

__global__ void __launch_bounds__(TPB, 2)
fused_mma_kernel(const float* __restrict__ x0, const float* __restrict__ x1,
                 const float* __restrict__ x2,
                 const float* __restrict__ b1_0, const float* __restrict__ b2_0,
                 const float* __restrict__ b1_1, const float* __restrict__ b2_1,
                 const float* __restrict__ b1_2, const float* __restrict__ b2_2,
                 float* __restrict__ out)
{
    extern __shared__ char smc[];
    const int tid  = threadIdx.x;
    const int w    = tid >> 5;
    const int lane = tid & 31;

    // ---- level select (tiles of 64 px: 1024 | 256 | 64) ----
    const int t = blockIdx.x;
    const float *x, *b1, *b2;
    float* o;
    int npix, tl, lvl;
    if (t < 1024)      { x = x0; b1 = b1_0; b2 = b2_0; o = out;             npix = 16384; tl = t;        lvl = 0; }
    else if (t < 1280) { x = x1; b1 = b1_1; b2 = b2_1; o = out + 16777216L; npix = 4096;  tl = t - 1024; lvl = 1; }
    else               { x = x2; b1 = b1_2; b2 = b2_2; o = out + 20971520L; npix = 1024;  tl = t - 1280; lvl = 2; }

    const int tpi  = npix / NT;
    const int img  = tl / tpi;
    const int p0   = (tl - img * tpi) * NT;
    const long ibase = (long)img * C_IN * npix + p0;

    uint4*  sXf = (uint4*)(smc + XF_OFF);
    uint4*  sZf = (uint4*)(smc + ZF_OFF);
    float*  sSc = (float*)(smc + SC_OFF);
    float4* sRb = (float4*)(smc + RB_OFF);

    // ================= stage X fragments (hi/lo fused in uint4) =================
    #pragma unroll
    for (int it = 0; it < 4; ++it) {
        const int idx = tid + it * TPB;
        const int kp = idx & 3, j = (idx >> 2) & 1, nt = (idx >> 3) & 7, ks = idx >> 6;
        const int c0 = ks * 16 + 2 * kp;
        const int p  = nt * 8 + 4 * j;
        const float4 r0 = *(const float4*)(x + ibase + (long)(c0    ) * npix + p);
        const float4 r1 = *(const float4*)(x + ibase + (long)(c0 + 1) * npix + p);
        const float4 r2 = *(const float4*)(x + ibase + (long)(c0 + 8) * npix + p);
        const float4 r3 = *(const float4*)(x + ibase + (long)(c0 + 9) * npix + p);
        const float v0[4] = {r0.x, r0.y, r0.z, r0.w};
        const float v1[4] = {r1.x, r1.y, r1.z, r1.w};
        const float v2[4] = {r2.x, r2.y, r2.z, r2.w};
        const float v3[4] = {r3.x, r3.y, r3.z, r3.w};
        const int base = (ks * 8 + nt) * 32;
        #pragma unroll
        for (int q = 0; q < 4; ++q) {
            const uint2 p01 = split_pair(v0[q], v1[q]);
            const uint2 p23 = split_pair(v2[q], v3[q]);
            sXf[base + (4 * j + q) * 4 + kp] = make_uint4(p01.x, p23.x, p01.y, p23.y);
        }
    }
    __syncthreads();

    // ======= phase 1 MMA: K-split. warp = (wr mt-pair, nh N-half, kh K-half) =======
    const int wr = w & 1;
    const int nh = (w >> 1) & 1;
    const int kh = w >> 2;
    float acc1[32];                  // [i(2)][j(4)][4]
    {
        #pragma unroll
        for (int i = 0; i < 32; ++i) acc1[i] = 0.0f;
        const uint4* Ah = g_A1h + ((lvl * 4 + wr * 2) * 16) * 32 + lane;
        const uint4* Al = g_A1l + ((lvl * 4 + wr * 2) * 16) * 32 + lane;
        #pragma unroll 4
        for (int k8 = 0; k8 < 8; ++k8) {
            const int ks = kh * 8 + k8;
            const uint4 ah0 = __ldg(Ah + ks * 32);
            const uint4 al0 = __ldg(Al + ks * 32);
            const uint4 ah1 = __ldg(Ah + (16 + ks) * 32);
            const uint4 al1 = __ldg(Al + (16 + ks) * 32);
            #pragma unroll
            for (int j = 0; j < 4; ++j) {
                const uint4 f = sXf[(ks * 8 + nh * 4 + j) * 32 + lane];
                mma_bf(acc1 + j * 4,      ah0, f.x, f.y);
                mma_bf(acc1 + 16 + j * 4, ah1, f.x, f.y);
                mma_bf(acc1 + j * 4,      ah0, f.z, f.w);
                mma_bf(acc1 + 16 + j * 4, ah1, f.z, f.w);
                mma_bf(acc1 + j * 4,      al0, f.x, f.y);
                mma_bf(acc1 + 16 + j * 4, al1, f.x, f.y);
            }
        }
    }
    __syncthreads();   // XF reads done; region reusable

    // ---- K-split reduction: kh=1 warps park partials in smem ----
    if (kh == 1) {
        #pragma unroll
        for (int i = 0; i < 2; ++i)
            #pragma unroll
            for (int j = 0; j < 4; ++j)
                sRb[((((wr * 2 + nh) * 2) + i) * 4 + j) * 32 + lane] =
                    make_float4(acc1[i * 16 + j * 4 + 0], acc1[i * 16 + j * 4 + 1],
                                acc1[i * 16 + j * 4 + 2], acc1[i * 16 + j * 4 + 3]);
    }
    __syncthreads();

    // ---- kh=0 warps: add partials + bias -> y scratch [64][68] ----
    if (kh == 0) {
        #pragma unroll
        for (int i = 0; i < 2; ++i) {
            const int r0 = (wr * 2 + i) * 16 + (lane >> 2), r1 = r0 + 8;
            const float bias0 = __ldg(b1 + r0);
            const float bias1 = __ldg(b1 + r1);
            #pragma unroll
            for (int j = 0; j < 4; ++j) {
                const float4 p = sRb[((((wr * 2 + nh) * 2) + i) * 4 + j) * 32 + lane];
                const int col = (nh * 4 + j) * 8 + (lane & 3) * 2;
                const float* a = acc1 + i * 16 + j * 4;
                *(float2*)(sSc + r0 * 68 + col) =
                    make_float2(a[0] + p.x + bias0, a[1] + p.y + bias0);
                *(float2*)(sSc + r1 * 68 + col) =
                    make_float2(a[2] + p.z + bias1, a[3] + p.w + bias1);
            }
        }
    }
    __syncthreads();

    // ---- build Z fragments: rows 0..63 = y, 64..95 = relu(y[32..63]) ----
    #pragma unroll
    for (int it = 0; it < 2; ++it) {
        const int idx = tid + it * TPB;
        if (idx < 384) {
            const int kp = idx & 3, j = (idx >> 2) & 1, nt = (idx >> 3) & 7, ks = idx >> 6;
            const int p = nt * 8 + 4 * j;
            float v[4][4];
            #pragma unroll
            for (int e = 0; e < 4; ++e) {
                const int zc = ks * 16 + 2 * kp + ((e >> 1) ? 8 : 0) + (e & 1);
                const int yr = (zc < 64) ? zc : (zc - 32);
                float4 yv = *(const float4*)(sSc + yr * 68 + p);
                if (zc >= 64) {
                    yv.x = fmaxf(yv.x, 0.f); yv.y = fmaxf(yv.y, 0.f);
                    yv.z = fmaxf(yv.z, 0.f); yv.w = fmaxf(yv.w, 0.f);
                }
                v[e][0] = yv.x; v[e][1] = yv.y; v[e][2] = yv.z; v[e][3] = yv.w;
            }
            const int base = (ks * 8 + nt) * 32;
            #pragma unroll
            for (int q = 0; q < 4; ++q) {
                const uint2 p01 = split_pair(v[0][q], v[1][q]);
                const uint2 p23 = split_pair(v[2][q], v[3][q]);
                sZf[base + (4 * j + q) * 4 + kp] = make_uint4(p01.x, p23.x, p01.y, p23.y);
            }
        }
    }
    __syncthreads();

    // ======= phase 2: warp owns M=32 (mt pair w) x all N=64, two halves of 4 nt =======
    {
        const uint4* Ah = g_A2h + ((lvl * 16 + w * 2) * 6) * 32 + lane;
        const uint4* Al = g_A2l + ((lvl * 16 + w * 2) * 6) * 32 + lane;
        const int ch0 = (w * 2) * 16 + (lane >> 2);
        const float bias00 = __ldg(b2 + ch0);
        const float bias01 = __ldg(b2 + ch0 + 8);
        const float bias10 = __ldg(b2 + ch0 + 16);
        const float bias11 = __ldg(b2 + ch0 + 24);

        #pragma unroll
        for (int iter = 0; iter < 2; ++iter) {
            float acc2[32];                      // [i(2)][n(4)][4]
            #pragma unroll
            for (int i = 0; i < 32; ++i) acc2[i] = 0.0f;

            #pragma unroll
            for (int ks = 0; ks < 6; ++ks) {
                const uint4 ah0 = __ldg(Ah + ks * 32);
                const uint4 al0 = __ldg(Al + ks * 32);
                const uint4 ah1 = __ldg(Ah + (6 + ks) * 32);
                const uint4 al1 = __ldg(Al + (6 + ks) * 32);
                #pragma unroll
                for (int n = 0; n < 4; ++n) {
                    const int nt = iter * 4 + n;
                    const uint4 f = sZf[(ks * 8 + nt) * 32 + lane];
                    mma_bf(acc2 + n * 4,      ah0, f.x, f.y);
                    mma_bf(acc2 + 16 + n * 4, ah1, f.x, f.y);
                    mma_bf(acc2 + n * 4,      ah0, f.z, f.w);
                    mma_bf(acc2 + 16 + n * 4, ah1, f.z, f.w);
                    mma_bf(acc2 + n * 4,      al0, f.x, f.y);
                    mma_bf(acc2 + 16 + n * 4, al1, f.x, f.y);
                }
            }

            // epilogue for this 32-px half
            #pragma unroll
            for (int i = 0; i < 2; ++i) {
                const int cA = ch0 + i * 16, cB = cA + 8;
                const float bA = i ? bias10 : bias00;
                const float bB = i ? bias11 : bias01;
                float* oA = o + ibase + (long)cA * npix;
                float* oB = o + ibase + (long)cB * npix;
                #pragma unroll
                for (int n = 0; n < 4; ++n) {
                    const int px = (iter * 4 + n) * 8 + (lane & 3) * 2;
                    const float* a = acc2 + i * 16 + n * 4;
                    *(float2*)(oA + px) = make_float2(a[0] + bA, a[1] + bA);
                    *(float2*)(oB + px) = make_float2(a[2] + bB, a[3] + bB);
                }
            }
        }
    }
}

extern "C" void kernel_launch(void* const* d_in, const int* in_sizes, int n_in,
                              void* d_out, int out_size)
{
    const float* x0   = (const float*)d_in[0];
    const float* x1   = (const float*)d_in[1];
    const float* x2   = (const float*)d_in[2];
    const float* W1_0 = (const float*)d_in[3];
    const float* b1_0 = (const float*)d_in[4];
    const float* W2_0 = (const float*)d_in[5];
    const float* b2_0 = (const float*)d_in[6];
    const float* W1_1 = (const float*)d_in[7];
    const float* b1_1 = (const float*)d_in[8];
    const float* W2_1 = (const float*)d_in[9];
    const float* b2_1 = (const float*)d_in[10];
    const float* W1_2 = (const float*)d_in[11];
    const float* b1_2 = (const float*)d_in[12];
    const float* W2_2 = (const float*)d_in[13];
    const float* b2_2 = (const float*)d_in[14];

    const int total = 3 * 4 * 16 * 32 + 3 * 16 * 6 * 32;
    prep_kernel<<<(total + 255) / 256, 256>>>(W1_0, W1_1, W1_2, W2_0, W2_1, W2_2);

    cudaFuncSetAttribute(fused_mma_kernel,
                         cudaFuncAttributeMaxDynamicSharedMemorySize, SMEM_BYTES);

    // 1344 tiles of 64 pixels: 1024 (level0) + 256 (level1) + 64 (level2)
    fused_mma_kernel<<<1344, TPB, SMEM_BYTES>>>(
        x0, x1, x2,
        b1_0, b2_0, b1_1, b2_1, b1_2, b2_2,
        (float*)d_out);
}